// round 9
// baseline (speedup 1.0000x reference)
#include <cuda_runtime.h>
#include <math.h>

// Problem constants (fixed shapes from reference setup_inputs)
#define BATCH 4
#define NPTS  8192
#define ALPHA 1000.0f

// 1D x-binning: 4096 bins of width 8/4096 over [-4,4), clamped
#define NBIN   4096
#define BINW   0.001953125f
#define CHSZ   32
#define NCHUNK (NPTS / CHSZ)      // 256
#define MARGIN 1e-4f

// ---------------------------------------------------------------------------
// Scratch (__device__ globals; no allocation allowed)
// arr index a: 0 = xyz1 (pred), 1 = xyz2 (gt)
// ---------------------------------------------------------------------------
__device__ float4 g_pts   [2][BATCH][NPTS];   // x-sorted (x,y,z,|p|^2)
__device__ int    g_orig  [2][BATCH][NPTS];   // sorted pos -> original index
__device__ int    g_bin   [2][BATCH][NPTS];   // original index -> bin
__device__ int    g_hist  [2][BATCH][NBIN];
__device__ int    g_start [2][BATCH][NBIN + 1];
__device__ int    g_cursor[2][BATCH][NBIN];
// dir 0: queries = xyz2 (gt), refs = xyz1 (pred); dir 1: swapped
__device__ float  g_dist[2][BATCH][NPTS];
__device__ int    g_idx [2][BATCH][NPTS];
__device__ int    g_cnt [2][BATCH][NPTS];

__device__ __forceinline__ int xbin(float x) {
    int c = (int)floorf((x + 4.0f) * 512.0f);
    return min(NBIN - 1, max(0, c));
}
__device__ __forceinline__ float binlo(int c) {
    return (float)c * BINW - 4.0f;
}

// ---------------------------------------------------------------------------
// K0: zero histograms, counts, output
// ---------------------------------------------------------------------------
__global__ void dacd_zero_kernel(float* __restrict__ out) {
    int t = blockIdx.x * blockDim.x + threadIdx.x;
    if (t < 2 * BATCH * NPTS) ((int*)g_cnt)[t] = 0;
    if (t < 2 * BATCH * NBIN) ((int*)g_hist)[t] = 0;
    if (t == 0) out[0] = 0.0f;
}

// ---------------------------------------------------------------------------
// K1: x-bin ids + histogram
// ---------------------------------------------------------------------------
__global__ void dacd_hist_kernel(const float* __restrict__ xyz1,
                                 const float* __restrict__ xyz2) {
    int t = blockIdx.x * blockDim.x + threadIdx.x;
    if (t >= 2 * BATCH * NPTS) return;
    const int a   = t / (BATCH * NPTS);
    const int rem = t % (BATCH * NPTS);
    const int b   = rem / NPTS;
    const int j   = rem % NPTS;
    const float* src = (a == 0) ? xyz1 : xyz2;
    float x = src[((size_t)b * NPTS + j) * 3 + 0];
    int bn = xbin(x);
    g_bin[a][b][j] = bn;
    atomicAdd(&g_hist[a][b][bn], 1);
}

// ---------------------------------------------------------------------------
// K2: exclusive scan of 4096-entry histogram per set (8 blocks x 1024 thr)
// ---------------------------------------------------------------------------
__global__ void __launch_bounds__(1024)
dacd_scan_kernel() {
    const int a = blockIdx.x >> 2;
    const int b = blockIdx.x & 3;
    const int tid = threadIdx.x;
    __shared__ int sh[1024];

    int h[4];
    int tot = 0;
    #pragma unroll
    for (int i = 0; i < 4; i++) {
        h[i] = g_hist[a][b][tid * 4 + i];
        tot += h[i];
    }
    sh[tid] = tot;
    __syncthreads();
    #pragma unroll
    for (int off = 1; off < 1024; off <<= 1) {
        int v = (tid >= off) ? sh[tid - off] : 0;
        __syncthreads();
        sh[tid] += v;
        __syncthreads();
    }
    int base = sh[tid] - tot;
    #pragma unroll
    for (int i = 0; i < 4; i++) {
        g_start [a][b][tid * 4 + i] = base;
        g_cursor[a][b][tid * 4 + i] = base;
        base += h[i];
    }
    if (tid == 1023) g_start[a][b][NBIN] = base;   // == NPTS
}

// ---------------------------------------------------------------------------
// K3: scatter points into x-bin-sorted order
// ---------------------------------------------------------------------------
__global__ void dacd_scatter_kernel(const float* __restrict__ xyz1,
                                    const float* __restrict__ xyz2) {
    int t = blockIdx.x * blockDim.x + threadIdx.x;
    if (t >= 2 * BATCH * NPTS) return;
    const int a   = t / (BATCH * NPTS);
    const int rem = t % (BATCH * NPTS);
    const int b   = rem / NPTS;
    const int j   = rem % NPTS;
    const float* src = (a == 0) ? xyz1 : xyz2;
    float x = src[((size_t)b * NPTS + j) * 3 + 0];
    float y = src[((size_t)b * NPTS + j) * 3 + 1];
    float z = src[((size_t)b * NPTS + j) * 3 + 2];
    int bn  = g_bin[a][b][j];
    int pos = atomicAdd(&g_cursor[a][b][bn], 1);
    g_pts [a][b][pos] = make_float4(x, y, z, x * x + y * y + z * z);
    g_orig[a][b][pos] = j;
}

// ---------------------------------------------------------------------------
// K4: exact NN via 1D window scan over the x-sorted ref array.
// One warp = 32 consecutive x-sorted queries. Scan 32-point chunks alternately
// right/left from the warp's own x position; the dense inner loop is identical
// to the proven brute-force loop (3 FFMA + FMNMX per pair, uniform L1 loads).
// Stop a side when the remaining points' guaranteed x separation from the warp
// x-range squared exceeds wmax + MARGIN. Bin-sorted order gives: points after
// position p have x >= binlo(bin(x_p)); points before p have
// x <= binlo(bin(x_p)) + BINW. Geometric: skipped dist^2 >= dx^2 > best+MARGIN
// while computed-value error << MARGIN -> exact (validated rel_err 0.0 in R7).
// Winning chunk replayed for min-original-index among value ties (jnp.argmin).
// ---------------------------------------------------------------------------
__global__ void __launch_bounds__(256)
dacd_nn_kernel() {
    const int lane  = threadIdx.x & 31;
    const int W     = blockIdx.x * 8 + (threadIdx.x >> 5);   // 0..2047
    const int dir   = W >> 10;
    const int b     = (W >> 8) & 3;
    const int chunk = W & 255;
    const int qarr  = 1 - dir;   // dir0 queries = xyz2 (arr 1)
    const int rarr  = dir;       // dir0 refs    = xyz1 (arr 0)

    const int si = chunk * 32 + lane;
    const float4 q  = g_pts [qarr][b][si];
    const int    oi = g_orig[qarr][b][si];
    const float mx = -2.0f * q.x, my = -2.0f * q.y, mz = -2.0f * q.z;

    // warp x-range (queries are x-sorted: lanes 0/31 bracket, but reduce anyway)
    float wx0 = q.x, wx1 = q.x;
    #pragma unroll
    for (int off = 16; off > 0; off >>= 1) {
        wx0 = fminf(wx0, __shfl_xor_sync(0xFFFFFFFFu, wx0, off));
        wx1 = fmaxf(wx1, __shfl_xor_sync(0xFFFFFFFFu, wx1, off));
    }

    const float4* __restrict__ refs = &g_pts[rarr][b][0];

    // start chunk: ref position of the warp-median query x
    int qb = __shfl_sync(0xFFFFFFFFu, xbin(q.x), 16);
    int c0 = min(NCHUNK - 1, max(0, g_start[rarr][b][qb] >> 5));

    float bestd = INFINITY;     // d' = |r|^2 - 2 q.r
    float wmax  = INFINITY;     // warp max of (q.w + bestd)
    int   bestc = c0;

    // scan one chunk; returns first/last x (warp-uniform: all lanes load same)
    float xf = 0.0f, xl = 0.0f;
    auto scan_chunk = [&](int c) {
        const float4* p = &refs[c * CHSZ];
        const float pre = bestd;
        #pragma unroll 8
        for (int k = 0; k < CHSZ; k++) {
            float4 v = __ldg(&p[k]);
            if (k == 0)        xf = v.x;
            if (k == CHSZ - 1) xl = v.x;
            float d = fmaf(mx, v.x, fmaf(my, v.y, fmaf(mz, v.z, v.w)));
            bestd = fminf(bestd, d);
        }
        const bool imp = (bestd < pre);
        if (imp) bestc = c;
        if (__any_sync(0xFFFFFFFFu, imp)) {
            float m = q.w + bestd;
            #pragma unroll
            for (int off = 16; off > 0; off >>= 1)
                m = fmaxf(m, __shfl_xor_sync(0xFFFFFFFFu, m, off));
            wmax = m;
        }
    };

    int rc = c0, lc = c0 - 1;
    bool rdone = false, ldone = (lc < 0);

    #pragma unroll 1
    while (!rdone || !ldone) {
        if (!rdone) {
            scan_chunk(rc);
            // all points beyond rc have x >= binlo(bin(xf))
            float xb = binlo(xbin(xf));
            float dx = xb - wx1;
            if (dx > 0.0f && dx * dx > wmax + MARGIN) rdone = true;
            if (++rc >= NCHUNK) rdone = true;
        }
        if (!ldone) {
            scan_chunk(lc);
            // all points before lc have x <= binlo(bin(xl)) + BINW
            float xb = binlo(xbin(xl)) + BINW;
            float dx = wx0 - xb;
            if (dx > 0.0f && dx * dx > wmax + MARGIN) ldone = true;
            if (--lc < 0) ldone = true;
        }
    }

    // replay winning chunk: min ORIGINAL index among value ties (= jnp.argmin)
    const int base = bestc * CHSZ;
    int bj = 0x7FFFFFFF;
    #pragma unroll 8
    for (int k = 0; k < CHSZ; k++) {
        float4 v = refs[base + k];
        float d = fmaf(mx, v.x, fmaf(my, v.y, fmaf(mz, v.z, v.w)));
        if (d == bestd) bj = min(bj, g_orig[rarr][b][base + k]);
    }

    g_dist[dir][b][oi] = q.w + bestd;
    g_idx [dir][b][oi] = bj;
    atomicAdd(&g_cnt[dir][b][bj], 1);
}

// ---------------------------------------------------------------------------
// K5: density-aware weighting + reduction to scalar.
// frac_21 = 1.0 exactly; ceil(frac_21) = 1.
// weight1 = 1 / max(1/c + 1e-6, 1),  weight2 = 1 / (c + 1e-6)
// out = sum (1 - exp(-alpha*d) * w) / (2*B*N)
// ---------------------------------------------------------------------------
__global__ void __launch_bounds__(256)
dacd_loss_kernel(float* __restrict__ out) {
    const int t = blockIdx.x * blockDim.x + threadIdx.x;
    const int dir = t / (BATCH * NPTS);
    const int rem = t % (BATCH * NPTS);
    const int b = rem / NPTS;
    const int i = rem % NPTS;

    float dist = g_dist[dir][b][i];
    int   idx  = g_idx [dir][b][i];
    float c    = (float)g_cnt[dir][b][idx];

    float w;
    if (dir == 0) {
        w = 1.0f / fmaxf(1.0f / c + 1e-6f, 1.0f);
    } else {
        w = 1.0f / (c + 1e-6f);
    }

    float e = expf(-dist * ALPHA);
    float contrib = (1.0f - e * w) * (1.0f / (2.0f * BATCH * NPTS));

    #pragma unroll
    for (int off = 16; off > 0; off >>= 1)
        contrib += __shfl_down_sync(0xFFFFFFFFu, contrib, off);

    __shared__ float warp_sums[8];
    const int lane = threadIdx.x & 31;
    const int wid  = threadIdx.x >> 5;
    if (lane == 0) warp_sums[wid] = contrib;
    __syncthreads();

    if (wid == 0) {
        float s = (lane < 8) ? warp_sums[lane] : 0.0f;
        #pragma unroll
        for (int off = 4; off > 0; off >>= 1)
            s += __shfl_down_sync(0xFFFFFFFFu, s, off);
        if (lane == 0) atomicAdd(out, s);
    }
}

// ---------------------------------------------------------------------------
// Launch
// ---------------------------------------------------------------------------
extern "C" void kernel_launch(void* const* d_in, const int* in_sizes, int n_in,
                              void* d_out, int out_size) {
    const float* xyz1 = (const float*)d_in[0];  // prediction [4,8192,3]
    const float* xyz2 = (const float*)d_in[1];  // ground truth [4,8192,3]
    float* out = (float*)d_out;

    (void)in_sizes; (void)n_in; (void)out_size;

    const int total = 2 * BATCH * NPTS;          // 65536

    dacd_zero_kernel    <<<(total + 255) / 256, 256>>>(out);
    dacd_hist_kernel    <<<(total + 255) / 256, 256>>>(xyz1, xyz2);
    dacd_scan_kernel    <<<2 * BATCH, 1024>>>();
    dacd_scatter_kernel <<<(total + 255) / 256, 256>>>(xyz1, xyz2);

    dacd_nn_kernel<<<256, 256>>>();              // 2048 warps

    dacd_loss_kernel<<<total / 256, 256>>>(out);
}

// round 10
// speedup vs baseline: 3.5414x; 3.5414x over previous
#include <cuda_runtime.h>
#include <math.h>

// Problem constants (fixed shapes from reference setup_inputs)
#define BATCH 4
#define NPTS  8192
#define ALPHA 1000.0f

// 2D serpentine column grid on (x,y): 64x64 cells of width 0.125 on [-4,4).
#define GDIM   64
#define CELLW  0.125f
#define NCOL   (GDIM * GDIM)
#define KRECT  2                                  // pass-A rectangle expansion
#define BOUND  (KRECT * CELLW * KRECT * CELLW)    // 0.0625
#define MARGIN 1e-4f

// ---------------------------------------------------------------------------
// Scratch (__device__ globals; no allocation allowed)
// arr index a: 0 = xyz1 (pred), 1 = xyz2 (gt)
// ---------------------------------------------------------------------------
__device__ float4 g_pts   [2][BATCH][NPTS];      // column-sorted (x,y,z,|p|^2)
__device__ int    g_orig  [2][BATCH][NPTS];
__device__ int    g_colid [2][BATCH][NPTS];
__device__ int    g_hist  [2][BATCH][NCOL];
__device__ int    g_start [2][BATCH][NCOL + 1];
__device__ int    g_cursor[2][BATCH][NCOL];
// dir 0: queries = xyz2 (gt), refs = xyz1 (pred); dir 1: swapped
__device__ float  g_dist[2][BATCH][NPTS];
__device__ int    g_idx [2][BATCH][NPTS];
__device__ int    g_cnt [2][BATCH][NPTS];
// fallback queue: packed (dir<<15 | b<<13 | si)
__device__ int    g_fbq[2 * BATCH * NPTS];
__device__ int    g_fbn;

__device__ __forceinline__ int cell_coord(float x) {
    int c = (int)floorf(x * 8.0f) + 32;
    return min(GDIM - 1, max(0, c));
}
__device__ __forceinline__ int serp_col(int cx, int cy) {
    return cx * GDIM + ((cx & 1) ? (GDIM - 1 - cy) : cy);
}

// ---------------------------------------------------------------------------
// K0: zero histograms, counts, queue counter, output
// ---------------------------------------------------------------------------
__global__ void dacd_zero_kernel(float* __restrict__ out) {
    int t = blockIdx.x * blockDim.x + threadIdx.x;
    if (t < 2 * BATCH * NPTS) ((int*)g_cnt)[t] = 0;
    if (t < 2 * BATCH * NCOL) ((int*)g_hist)[t] = 0;
    if (t == 0) { out[0] = 0.0f; g_fbn = 0; }
}

// ---------------------------------------------------------------------------
// K1: serpentine column ids + histogram
// ---------------------------------------------------------------------------
__global__ void dacd_hist_kernel(const float* __restrict__ xyz1,
                                 const float* __restrict__ xyz2) {
    int t = blockIdx.x * blockDim.x + threadIdx.x;
    if (t >= 2 * BATCH * NPTS) return;
    const int a   = t / (BATCH * NPTS);
    const int rem = t % (BATCH * NPTS);
    const int b   = rem / NPTS;
    const int j   = rem % NPTS;
    const float* src = (a == 0) ? xyz1 : xyz2;
    float x = src[((size_t)b * NPTS + j) * 3 + 0];
    float y = src[((size_t)b * NPTS + j) * 3 + 1];
    int col = serp_col(cell_coord(x), cell_coord(y));
    g_colid[a][b][j] = col;
    atomicAdd(&g_hist[a][b][col], 1);
}

// ---------------------------------------------------------------------------
// K2: exclusive scan of 4096-entry histogram per set (8 blocks x 1024 thr)
// ---------------------------------------------------------------------------
__global__ void __launch_bounds__(1024)
dacd_scan_kernel() {
    const int a = blockIdx.x >> 2;
    const int b = blockIdx.x & 3;
    const int tid = threadIdx.x;
    __shared__ int sh[1024];

    int h[4];
    int tot = 0;
    #pragma unroll
    for (int i = 0; i < 4; i++) {
        h[i] = g_hist[a][b][tid * 4 + i];
        tot += h[i];
    }
    sh[tid] = tot;
    __syncthreads();
    #pragma unroll
    for (int off = 1; off < 1024; off <<= 1) {
        int v = (tid >= off) ? sh[tid - off] : 0;
        __syncthreads();
        sh[tid] += v;
        __syncthreads();
    }
    int base = sh[tid] - tot;
    #pragma unroll
    for (int i = 0; i < 4; i++) {
        g_start [a][b][tid * 4 + i] = base;
        g_cursor[a][b][tid * 4 + i] = base;
        base += h[i];
    }
    if (tid == 1023) g_start[a][b][NCOL] = base;   // == NPTS
}

// ---------------------------------------------------------------------------
// K3: scatter points into serpentine-column-sorted order
// ---------------------------------------------------------------------------
__global__ void dacd_scatter_kernel(const float* __restrict__ xyz1,
                                    const float* __restrict__ xyz2) {
    int t = blockIdx.x * blockDim.x + threadIdx.x;
    if (t >= 2 * BATCH * NPTS) return;
    const int a   = t / (BATCH * NPTS);
    const int rem = t % (BATCH * NPTS);
    const int b   = rem / NPTS;
    const int j   = rem % NPTS;
    const float* src = (a == 0) ? xyz1 : xyz2;
    float x = src[((size_t)b * NPTS + j) * 3 + 0];
    float y = src[((size_t)b * NPTS + j) * 3 + 1];
    float z = src[((size_t)b * NPTS + j) * 3 + 2];
    int col = g_colid[a][b][j];
    int pos = atomicAdd(&g_cursor[a][b][col], 1);
    g_pts [a][b][pos] = make_float4(x, y, z, x * x + y * y + z * z);
    g_orig[a][b][pos] = j;
}

// ---------------------------------------------------------------------------
// K4a: pass A — fixed rectangle (warp box + KRECT cells), one contiguous run
// per x-row. If a lane's true squared distance <= BOUND - eps it is provably
// the global NN (unscanned points differ by >= KRECT*CELLW in x or y; clamped
// border cells only push points farther). Converged lanes finalize; the rest
// are appended to the fallback queue.
// ---------------------------------------------------------------------------
__global__ void __launch_bounds__(256)
dacd_nn_grid_kernel() {
    const int lane  = threadIdx.x & 31;
    const int W     = blockIdx.x * 8 + (threadIdx.x >> 5);   // 0..2047
    const int dir   = W >> 10;
    const int b     = (W >> 8) & 3;
    const int chunk = W & 255;
    const int qarr  = 1 - dir;
    const int rarr  = dir;

    const int si = chunk * 32 + lane;
    const float4 q  = g_pts [qarr][b][si];
    const int    oi = g_orig[qarr][b][si];
    const float mx = -2.0f * q.x, my = -2.0f * q.y, mz = -2.0f * q.z;

    const int qcx = cell_coord(q.x);
    const int qcy = cell_coord(q.y);
    const int bx0 = (int)__reduce_min_sync(0xFFFFFFFFu, (unsigned)qcx);
    const int bx1 = (int)__reduce_max_sync(0xFFFFFFFFu, (unsigned)qcx);
    const int by0 = (int)__reduce_min_sync(0xFFFFFFFFu, (unsigned)qcy);
    const int by1 = (int)__reduce_max_sync(0xFFFFFFFFu, (unsigned)qcy);

    const int xlo = max(bx0 - KRECT, 0), xhi = min(bx1 + KRECT, GDIM - 1);
    const int ylo = max(by0 - KRECT, 0), yhi = min(by1 + KRECT, GDIM - 1);

    const float4* __restrict__ refs = &g_pts  [rarr][b][0];
    const int*    __restrict__ cs   = &g_start[rarr][b][0];

    float bestd = INFINITY;   // d' = |r|^2 - 2 q.r
    int   bestt = 0;

    #pragma unroll 1
    for (int cx = xlo; cx <= xhi; cx++) {
        int lo, hi;
        if (cx & 1) { lo = cx * GDIM + (GDIM - 1 - yhi); hi = cx * GDIM + (GDIM - 1 - ylo); }
        else        { lo = cx * GDIM + ylo;              hi = cx * GDIM + yhi; }
        const int s = cs[lo];
        const int e = cs[hi + 1];
        #pragma unroll 4
        for (int t = s; t < e; t++) {
            float4 v = __ldg(&refs[t]);
            float d = fmaf(mx, v.x, fmaf(my, v.y, fmaf(mz, v.z, v.w)));
            if (d < bestd) { bestd = d; bestt = t; }
        }
    }

    const float dtrue = q.w + bestd;
    const bool ok = dtrue <= (BOUND - MARGIN);

    if (ok) {
        const int bj = g_orig[rarr][b][bestt];
        g_dist[dir][b][oi] = dtrue;
        g_idx [dir][b][oi] = bj;
        atomicAdd(&g_cnt[dir][b][bj], 1);
    }
    // compact append of non-converged lanes
    const unsigned vote = __ballot_sync(0xFFFFFFFFu, !ok);
    if (vote) {
        int base = 0;
        if (lane == 0) base = atomicAdd(&g_fbn, __popc(vote));
        base = __shfl_sync(0xFFFFFFFFu, base, 0);
        if (!ok) {
            int off = __popc(vote & ((1u << lane) - 1u));
            g_fbq[base + off] = (dir << 15) | (b << 13) | si;
        }
    }
}

// ---------------------------------------------------------------------------
// K4b: pass B — expanding-rectangle exact NN for queued queries. One warp per
// query (grid-strided). For k in {4,8,16,64}: scan the (2k+1)^2 cell rectangle
// centered on the query's cell (lanes stride coalesced over each row-run),
// warp-reduce, stop when best <= (k*CELLW)^2 - MARGIN. Exact: any unscanned
// cell is >= k+1 index steps away in x or y => geometric separation >= k*CELLW
// (clamped border cells only push points farther). k=64 covers all points.
// ---------------------------------------------------------------------------
__global__ void __launch_bounds__(256)
dacd_nn_fallback_kernel() {
    const int lane = threadIdx.x & 31;
    const int wid  = blockIdx.x * 8 + (threadIdx.x >> 5);
    const int nw   = gridDim.x * 8;
    const int n    = g_fbn;

    const int KS[4] = {4, 8, 16, 64};

    for (int item = wid; item < n; item += nw) {
        const int pk  = g_fbq[item];
        const int dir = pk >> 15;
        const int b   = (pk >> 13) & 3;
        const int si  = pk & 0x1FFF;
        const int qarr = 1 - dir;
        const int rarr = dir;

        const float4 q  = g_pts [qarr][b][si];
        const int    oi = g_orig[qarr][b][si];
        const float mx = -2.0f * q.x, my = -2.0f * q.y, mz = -2.0f * q.z;
        const int cx0 = cell_coord(q.x);
        const int cy0 = cell_coord(q.y);

        const float4* __restrict__ refs = &g_pts  [rarr][b][0];
        const int*    __restrict__ cs   = &g_start[rarr][b][0];

        #pragma unroll 1
        for (int ki = 0; ki < 4; ki++) {
            const int k = KS[ki];
            const int xlo = max(cx0 - k, 0), xhi = min(cx0 + k, GDIM - 1);
            const int ylo = max(cy0 - k, 0), yhi = min(cy0 + k, GDIM - 1);

            float bestd = INFINITY;
            int   bestt = 0;
            #pragma unroll 1
            for (int cx = xlo; cx <= xhi; cx++) {
                int lo, hi;
                if (cx & 1) { lo = cx * GDIM + (GDIM - 1 - yhi); hi = cx * GDIM + (GDIM - 1 - ylo); }
                else        { lo = cx * GDIM + ylo;              hi = cx * GDIM + yhi; }
                const int s = cs[lo];
                const int e = cs[hi + 1];
                for (int t = s + lane; t < e; t += 32) {
                    float4 v = __ldg(&refs[t]);
                    float d = fmaf(mx, v.x, fmaf(my, v.y, fmaf(mz, v.z, v.w)));
                    if (d < bestd || (d == bestd && t < bestt)) { bestd = d; bestt = t; }
                }
            }
            // warp reduce (min d, tie -> min sorted pos)
            #pragma unroll
            for (int off = 16; off > 0; off >>= 1) {
                float od = __shfl_xor_sync(0xFFFFFFFFu, bestd, off);
                int   ot = __shfl_xor_sync(0xFFFFFFFFu, bestt, off);
                if (od < bestd || (od == bestd && ot < bestt)) { bestd = od; bestt = ot; }
            }
            const float kb = (float)k * CELLW;
            const bool covered = (xlo == 0 && ylo == 0 && xhi == GDIM - 1 && yhi == GDIM - 1);
            if ((q.w + bestd) <= (kb * kb - MARGIN) || covered) {
                if (lane == 0) {
                    const int bj = g_orig[rarr][b][bestt];
                    g_dist[dir][b][oi] = q.w + bestd;
                    g_idx [dir][b][oi] = bj;
                    atomicAdd(&g_cnt[dir][b][bj], 1);
                }
                break;
            }
        }
    }
}

// ---------------------------------------------------------------------------
// K5: density-aware weighting + reduction to scalar.
// frac_21 = 1.0 exactly; ceil(frac_21) = 1.
// weight1 = 1 / max(1/c + 1e-6, 1),  weight2 = 1 / (c + 1e-6)
// out = sum (1 - exp(-alpha*d) * w) / (2*B*N)
// ---------------------------------------------------------------------------
__global__ void __launch_bounds__(256)
dacd_loss_kernel(float* __restrict__ out) {
    const int t = blockIdx.x * blockDim.x + threadIdx.x;
    const int dir = t / (BATCH * NPTS);
    const int rem = t % (BATCH * NPTS);
    const int b = rem / NPTS;
    const int i = rem % NPTS;

    float dist = g_dist[dir][b][i];
    int   idx  = g_idx [dir][b][i];
    float c    = (float)g_cnt[dir][b][idx];

    float w;
    if (dir == 0) {
        w = 1.0f / fmaxf(1.0f / c + 1e-6f, 1.0f);
    } else {
        w = 1.0f / (c + 1e-6f);
    }

    float e = expf(-dist * ALPHA);
    float contrib = (1.0f - e * w) * (1.0f / (2.0f * BATCH * NPTS));

    #pragma unroll
    for (int off = 16; off > 0; off >>= 1)
        contrib += __shfl_down_sync(0xFFFFFFFFu, contrib, off);

    __shared__ float warp_sums[8];
    const int lane = threadIdx.x & 31;
    const int wid  = threadIdx.x >> 5;
    if (lane == 0) warp_sums[wid] = contrib;
    __syncthreads();

    if (wid == 0) {
        float s = (lane < 8) ? warp_sums[lane] : 0.0f;
        #pragma unroll
        for (int off = 4; off > 0; off >>= 1)
            s += __shfl_down_sync(0xFFFFFFFFu, s, off);
        if (lane == 0) atomicAdd(out, s);
    }
}

// ---------------------------------------------------------------------------
// Launch
// ---------------------------------------------------------------------------
extern "C" void kernel_launch(void* const* d_in, const int* in_sizes, int n_in,
                              void* d_out, int out_size) {
    const float* xyz1 = (const float*)d_in[0];  // prediction [4,8192,3]
    const float* xyz2 = (const float*)d_in[1];  // ground truth [4,8192,3]
    float* out = (float*)d_out;

    (void)in_sizes; (void)n_in; (void)out_size;

    const int total = 2 * BATCH * NPTS;          // 65536

    dacd_zero_kernel    <<<(total + 255) / 256, 256>>>(out);
    dacd_hist_kernel    <<<(total + 255) / 256, 256>>>(xyz1, xyz2);
    dacd_scan_kernel    <<<2 * BATCH, 1024>>>();
    dacd_scatter_kernel <<<(total + 255) / 256, 256>>>(xyz1, xyz2);

    dacd_nn_grid_kernel    <<<256, 256>>>();     // 2048 warps
    dacd_nn_fallback_kernel<<<256, 256>>>();     // 2048 warps, queue-strided

    dacd_loss_kernel<<<total / 256, 256>>>(out);
}